// round 1
// baseline (speedup 1.0000x reference)
#include <cuda_runtime.h>
#include <math.h>

// ---------------- problem constants ----------------
#define NB    32          // batch
#define LSEQ  192         // patches
#define SEQF  193         // with cls
#define DM    384         // d_model
#define DI    768         // d_inner
#define DS    16          // d_state
#define DTRK  24          // dt_rank
#define XPD   56          // dt_rank + 2*d_state
#define ROWS  (NB*LSEQ)   // 6144

// ---------------- scratch layout (floats) ----------------
// pr:    6144*384  = 2359296   @ 0
// xln:   6144*384  = 2359296   @ 2359296
// xz:    6144*1536 = 9437184   @ 4718592
// xc:    6144*768  = 4718592   @ 14155776
// xdbl:  6144*56   = 344064    @ 18874368
// dt:    6144*768  = 4718592   @ 19218432
// y:     6144*768  = 4718592   @ 23937024
// cat:   6144*768  = 4718592   @ 28655616
// fused: 6144*384  = 2359296   @ 33374208
// total 35733504 floats (~143MB)
__device__ float g_scratch[35733504];

#define OFF_PR     0
#define OFF_XLN    2359296
#define OFF_XZ     4718592
#define OFF_XC     14155776
#define OFF_XDBL   18874368
#define OFF_DT     19218432
#define OFF_Y      23937024
#define OFF_CAT    28655616
#define OFF_FUSED  33374208

// ---------------- gather: pr[b,t,:] = x[b, 1+scan_idx[t], :] ----------------
__global__ void gather_kernel(const float* __restrict__ X,
                              const int* __restrict__ scan_idx,
                              float* __restrict__ PR)
{
    int idx = blockIdx.x * blockDim.x + threadIdx.x;   // over ROWS*DM
    if (idx >= ROWS * DM) return;
    int c = idx % DM;
    int t = (idx / DM) % LSEQ;
    int b = idx / (DM * LSEQ);
    int src = scan_idx[t];
    PR[idx] = X[((size_t)b * SEQF + 1 + src) * DM + c];
}

// ---------------- layernorm over DM=384, one block (128 thr) per row ----------------
__global__ __launch_bounds__(128) void ln_kernel(const float* __restrict__ X,
                                                 const float* __restrict__ G,
                                                 const float* __restrict__ Bb,
                                                 float* __restrict__ Y)
{
    int row = blockIdx.x;
    const float* x = X + (size_t)row * DM;
    float v[3]; float s = 0.f, ss = 0.f;
    #pragma unroll
    for (int i = 0; i < 3; i++) {
        v[i] = x[threadIdx.x + i * 128];
        s += v[i]; ss += v[i] * v[i];
    }
    // block reduce (4 warps)
    __shared__ float sh_s[4], sh_ss[4];
    #pragma unroll
    for (int o = 16; o; o >>= 1) {
        s  += __shfl_down_sync(0xffffffffu, s,  o);
        ss += __shfl_down_sync(0xffffffffu, ss, o);
    }
    int wid = threadIdx.x >> 5, lid = threadIdx.x & 31;
    if (lid == 0) { sh_s[wid] = s; sh_ss[wid] = ss; }
    __syncthreads();
    float ts = sh_s[0] + sh_s[1] + sh_s[2] + sh_s[3];
    float tss = sh_ss[0] + sh_ss[1] + sh_ss[2] + sh_ss[3];
    float mean = ts * (1.f / DM);
    float var = tss * (1.f / DM) - mean * mean;
    float rstd = rsqrtf(var + 1e-5f);
    float* y = Y + (size_t)row * DM;
    #pragma unroll
    for (int i = 0; i < 3; i++) {
        int c = threadIdx.x + i * 128;
        y[c] = (v[i] - mean) * rstd * G[c] + Bb[c];
    }
}

// ---------------- generic SGEMM: C[M,N] = A[M,K] @ W[N,K]^T (+epilogue) ----------------
// EPI: 0 = none, 1 = +bias, 2 = +bias then softplus, 3 = +residual R
template<int EPI>
__global__ __launch_bounds__(256) void sgemm128(
    const float* __restrict__ A, int lda,
    const float* __restrict__ W, int K,
    const float* __restrict__ bias,
    const float* __restrict__ R, int ldr,
    float* __restrict__ C, int ldc, int N)
{
    __shared__ float As[8][128];
    __shared__ float Ws[8][128];
    int tid = threadIdx.x;
    int rowBase = blockIdx.y * 128;
    int colBase = blockIdx.x * 128;
    int ty = tid >> 4, tx = tid & 15;

    int arow = tid >> 1;
    int ak   = (tid & 1) * 4;
    int wn   = tid >> 1;
    int wk   = (tid & 1) * 4;

    float acc[8][8];
    #pragma unroll
    for (int i = 0; i < 8; i++)
        #pragma unroll
        for (int j = 0; j < 8; j++) acc[i][j] = 0.f;

    const float* Aptr = A + (size_t)(rowBase + arow) * lda + ak;
    bool wvalid = (colBase + wn) < N;
    const float* Wptr = W + (size_t)(colBase + wn) * K + wk;

    for (int k0 = 0; k0 < K; k0 += 8) {
        float4 av = *(const float4*)(Aptr + k0);
        float4 wv = wvalid ? *(const float4*)(Wptr + k0) : make_float4(0.f,0.f,0.f,0.f);
        __syncthreads();
        As[ak+0][arow] = av.x; As[ak+1][arow] = av.y;
        As[ak+2][arow] = av.z; As[ak+3][arow] = av.w;
        Ws[wk+0][wn] = wv.x; Ws[wk+1][wn] = wv.y;
        Ws[wk+2][wn] = wv.z; Ws[wk+3][wn] = wv.w;
        __syncthreads();
        #pragma unroll
        for (int k = 0; k < 8; k++) {
            float a[8], w[8];
            *(float4*)&a[0] = *(const float4*)&As[k][ty*8];
            *(float4*)&a[4] = *(const float4*)&As[k][ty*8+4];
            *(float4*)&w[0] = *(const float4*)&Ws[k][tx*8];
            *(float4*)&w[4] = *(const float4*)&Ws[k][tx*8+4];
            #pragma unroll
            for (int i = 0; i < 8; i++)
                #pragma unroll
                for (int j = 0; j < 8; j++)
                    acc[i][j] = fmaf(a[i], w[j], acc[i][j]);
        }
    }
    #pragma unroll
    for (int i = 0; i < 8; i++) {
        int row = rowBase + ty * 8 + i;
        #pragma unroll
        for (int j = 0; j < 8; j++) {
            int col = colBase + tx * 8 + j;
            if (col < N) {
                float v = acc[i][j];
                if (EPI == 1 || EPI == 2) v += bias[col];
                if (EPI == 2) v = (v > 20.f) ? v : log1pf(__expf(v));
                if (EPI == 3) v += R[(size_t)row * ldr + col];
                C[(size_t)row * ldc + col] = v;
            }
        }
    }
}

// ---------------- small-N GEMM (x_proj: N=56, K=768): BM=32, BN=64, BK=16 ----------------
__global__ __launch_bounds__(256) void sgemm_s(
    const float* __restrict__ A, int lda,
    const float* __restrict__ W, int K,
    float* __restrict__ C, int ldc, int N)
{
    __shared__ float As[16][32];
    __shared__ float Ws[16][64];
    int tid = threadIdx.x;
    int rowBase = blockIdx.y * 32;
    int colBase = blockIdx.x * 64;
    int ty = tid >> 4, tx = tid & 15;
    float acc[2][4] = {{0.f,0.f,0.f,0.f},{0.f,0.f,0.f,0.f}};
    int wn = tid >> 2, wk = (tid & 3) * 4;
    bool wv = (colBase + wn) < N;

    for (int k0 = 0; k0 < K; k0 += 16) {
        __syncthreads();
        #pragma unroll
        for (int i = tid; i < 512; i += 256) {
            int r = i >> 4, k = i & 15;
            As[k][r] = A[(size_t)(rowBase + r) * lda + k0 + k];
        }
        float4 wvv = wv ? *(const float4*)&W[(size_t)(colBase + wn) * K + k0 + wk]
                        : make_float4(0.f,0.f,0.f,0.f);
        Ws[wk+0][wn] = wvv.x; Ws[wk+1][wn] = wvv.y;
        Ws[wk+2][wn] = wvv.z; Ws[wk+3][wn] = wvv.w;
        __syncthreads();
        #pragma unroll
        for (int k = 0; k < 16; k++) {
            float a0 = As[k][ty], a1 = As[k][ty + 16];
            float4 w4 = *(const float4*)&Ws[k][tx*4];
            acc[0][0] = fmaf(a0, w4.x, acc[0][0]);
            acc[0][1] = fmaf(a0, w4.y, acc[0][1]);
            acc[0][2] = fmaf(a0, w4.z, acc[0][2]);
            acc[0][3] = fmaf(a0, w4.w, acc[0][3]);
            acc[1][0] = fmaf(a1, w4.x, acc[1][0]);
            acc[1][1] = fmaf(a1, w4.y, acc[1][1]);
            acc[1][2] = fmaf(a1, w4.z, acc[1][2]);
            acc[1][3] = fmaf(a1, w4.w, acc[1][3]);
        }
    }
    #pragma unroll
    for (int i = 0; i < 2; i++) {
        int row = rowBase + ty + i * 16;
        #pragma unroll
        for (int j = 0; j < 4; j++) {
            int col = colBase + tx * 4 + j;
            if (col < N) C[(size_t)row * ldc + col] = acc[i][j];
        }
    }
}

// ---------------- causal depthwise conv (k=4) + SiLU; dir-aware ----------------
// fwd: xc[b,t,d] = silu(sum_j w[d,j]*xm[b,t-3+j,d] + bias[d])
// bwd: xc[b,t,d] = silu(sum_j w[d,j]*xm[b,t+3-j,d] + bias[d])
__global__ void conv_kernel(const float* __restrict__ XZ,
                            const float* __restrict__ Wc,
                            const float* __restrict__ Bc,
                            float* __restrict__ XC, int dir)
{
    int idx = blockIdx.x * blockDim.x + threadIdx.x;   // ROWS*DI
    if (idx >= ROWS * DI) return;
    int d = idx % DI;
    int t = (idx / DI) % LSEQ;
    int b = idx / (DI * LSEQ);
    const float* xm = XZ + (size_t)b * LSEQ * (2 * DI) + d;   // xm part: cols [0,768)
    float acc = Bc[d];
    #pragma unroll
    for (int j = 0; j < 4; j++) {
        int tt = (dir == 0) ? (t - 3 + j) : (t + 3 - j);
        if (tt >= 0 && tt < LSEQ)
            acc = fmaf(Wc[d * 4 + j], xm[(size_t)tt * (2 * DI)], acc);
    }
    acc = acc / (1.f + __expf(-acc));   // silu
    XC[idx] = acc;
}

// ---------------- selective scan, fused with +u*D and *silu(z) ----------------
// grid: (NB, 3) ; block 256 threads ; thread d = blockIdx.y*256 + tid
__global__ __launch_bounds__(256) void scan_kernel(
    const float* __restrict__ XC,     // u  (ROWS, DI)
    const float* __restrict__ DT,     // dt (ROWS, DI)
    const float* __restrict__ XDBL,   // (ROWS, 56): [dtr24 | B16 | C16]
    const float* __restrict__ XZ,     // (ROWS, 1536), z = cols[768:)
    const float* __restrict__ Alog,   // (DI, DS)
    const float* __restrict__ Dp,     // (DI)
    float* __restrict__ Y, int dir)
{
    __shared__ float Bs[LSEQ][DS];
    __shared__ float Cs[LSEQ][DS];
    int b = blockIdx.x;
    int d = blockIdx.y * 256 + threadIdx.x;

    const float* xd = XDBL + (size_t)b * LSEQ * XPD;
    for (int i = threadIdx.x; i < LSEQ * DS; i += 256) {
        int t = i / DS, n = i % DS;
        Bs[t][n] = xd[t * XPD + DTRK + n];
        Cs[t][n] = xd[t * XPD + DTRK + DS + n];
    }
    __syncthreads();

    float A[DS];
    #pragma unroll
    for (int n = 0; n < DS; n++) A[n] = -__expf(Alog[d * DS + n]);
    float Dd = Dp[d];
    float h[DS];
    #pragma unroll
    for (int n = 0; n < DS; n++) h[n] = 0.f;

    const float* ub  = XC + (size_t)b * LSEQ * DI + d;
    const float* dtb = DT + (size_t)b * LSEQ * DI + d;
    const float* zb  = XZ + (size_t)b * LSEQ * (2 * DI) + DI + d;
    float* yb = Y + (size_t)b * LSEQ * DI + d;

    for (int s = 0; s < LSEQ; s++) {
        int t = dir ? (LSEQ - 1 - s) : s;
        float dtv = dtb[(size_t)t * DI];
        float u   = ub[(size_t)t * DI];
        float du  = dtv * u;
        float accv = 0.f;
        #pragma unroll
        for (int n = 0; n < DS; n++) {
            float dA = __expf(dtv * A[n]);
            h[n] = fmaf(dA, h[n], du * Bs[t][n]);
            accv = fmaf(h[n], Cs[t][n], accv);
        }
        float z = zb[(size_t)t * (2 * DI)];
        float sz = z / (1.f + __expf(-z));
        yb[(size_t)t * DI] = (accv + u * Dd) * sz;
    }
}

// ---------------- final: scatter via inv_idx + cls passthrough ----------------
__global__ void final_kernel(const float* __restrict__ X,
                             const float* __restrict__ FUSED,
                             const int* __restrict__ inv_idx,
                             float* __restrict__ OUT)
{
    int idx = blockIdx.x * blockDim.x + threadIdx.x;   // NB*SEQF*DM
    if (idx >= NB * SEQF * DM) return;
    int c = idx % DM;
    int s = (idx / DM) % SEQF;
    int b = idx / (DM * SEQF);
    if (s == 0) {
        OUT[idx] = X[idx];
    } else {
        int src = inv_idx[s - 1];
        OUT[idx] = FUSED[((size_t)b * LSEQ + src) * DM + c];
    }
}

// ---------------- host launch ----------------
extern "C" void kernel_launch(void* const* d_in, const int* in_sizes, int n_in,
                              void* d_out, int out_size)
{
    float* S = nullptr;
    cudaGetSymbolAddress((void**)&S, g_scratch);

    float* pr    = S + OFF_PR;
    float* xln   = S + OFF_XLN;
    float* xz    = S + OFF_XZ;
    float* xc    = S + OFF_XC;
    float* xdbl  = S + OFF_XDBL;
    float* dtb   = S + OFF_DT;
    float* yb    = S + OFF_Y;
    float* catb  = S + OFF_CAT;
    float* fused = S + OFF_FUSED;

    const float* x        = (const float*)d_in[0];
    const float* fusion_w = (const float*)d_in[23];
    const float* fusion_b = (const float*)d_in[24];
    const int*   scan_idx = (const int*)d_in[25];
    const int*   inv_idx  = (const int*)d_in[26];

    gather_kernel<<<(ROWS*DM + 255)/256, 256>>>(x, scan_idx, pr);

    for (int dir = 0; dir < 2; dir++) {
        int base = 1 + dir * 11;
        const float* ln_g   = (const float*)d_in[base + 0];
        const float* ln_b   = (const float*)d_in[base + 1];
        const float* in_w   = (const float*)d_in[base + 2];   // (1536,384)
        const float* conv_w = (const float*)d_in[base + 3];   // (768,4)
        const float* conv_b = (const float*)d_in[base + 4];   // (768)
        const float* x_w    = (const float*)d_in[base + 5];   // (56,768)
        const float* dt_w   = (const float*)d_in[base + 6];   // (768,24)
        const float* dt_b   = (const float*)d_in[base + 7];   // (768)
        const float* A_log  = (const float*)d_in[base + 8];   // (768,16)
        const float* Dp     = (const float*)d_in[base + 9];   // (768)
        const float* out_w  = (const float*)d_in[base + 10];  // (384,768)

        ln_kernel<<<ROWS, 128>>>(pr, ln_g, ln_b, xln);

        // xz = xln @ in_w^T : (6144,384)x(384,1536)
        sgemm128<0><<<dim3(12, 48), 256>>>(xln, DM, in_w, DM,
                                           nullptr, nullptr, 0, xz, 2*DI, 2*DI);

        conv_kernel<<<(ROWS*DI + 255)/256, 256>>>(xz, conv_w, conv_b, xc, dir);

        // xdbl = xc @ x_w^T : (6144,768)x(768,56)
        sgemm_s<<<dim3(1, ROWS/32), 256>>>(xc, DI, x_w, DI, xdbl, XPD, XPD);

        // dt = softplus(dtr @ dt_w^T + dt_b) : (6144,24)x(24,768)
        sgemm128<2><<<dim3(6, 48), 256>>>(xdbl, XPD, dt_w, DTRK,
                                          dt_b, nullptr, 0, dtb, DI, DI);

        scan_kernel<<<dim3(NB, 3), 256>>>(xc, dtb, xdbl, xz, A_log, Dp, yb, dir);

        // out_dir = y @ out_w^T + pr, stored into cat[:, dir*384] (ldc=768)
        sgemm128<3><<<dim3(3, 48), 256>>>(yb, DI, out_w, DI,
                                          nullptr, pr, DM,
                                          catb + dir * DM, 2*DM, DM);
    }

    // fused = cat @ fusion_w^T + fusion_b : (6144,768)x(768,384)
    sgemm128<1><<<dim3(3, 48), 256>>>(catb, 2*DM, fusion_w, 2*DM,
                                      fusion_b, nullptr, 0, fused, DM, DM);

    final_kernel<<<(NB*SEQF*DM + 255)/256, 256>>>(x, fused, inv_idx, (float*)d_out);
}